// round 11
// baseline (speedup 1.0000x reference)
#include <cuda_runtime.h>
#include <cuda_bf16.h>
#include <cstdint>

#define N_NODES 100000
#define N_EDGES 1600000
#define FDIM    128
#define HEADS   8
#define EPS_F   1e-12f
#define ALPHA_F 0.2f

// Static device scratch (no runtime allocation).
// g_srcsum[n*16 + j] : j<8 -> s_src[n][j] ; j>=8 -> ssum[n][j-8] (raw sums).
//                      64B row per node: src scores + sums share a line.
// g_dst[n*8 + j]     : s_dst[n][j] (32B row).
__device__ __align__(128) float g_srcsum[N_NODES * 16];
__device__ __align__(128) float g_dst[N_NODES * 8];

// ---------------------------------------------------------------------------
// Kernel 1: per-node scores, two warps per node (role split src/dst), two
// nodes per iteration + software pipelining (next pair prefetched) ->
// steady-state MLP ~4/warp on the coalesced x stream.
// ---------------------------------------------------------------------------
__global__ void __launch_bounds__(256) scores_kernel(
    const float* __restrict__ x,
    const float* __restrict__ aa,
    int n_nodes)
{
    const int lane  = threadIdx.x & 31;
    const int gwarp = (blockIdx.x * blockDim.x + threadIdx.x) >> 5;
    const int nwarp = (gridDim.x * blockDim.x) >> 5;
    const int role  = gwarp & 1;            // 0: src rows, 1: dst rows
    const int wnode0 = gwarp >> 1;
    const int nstep  = nwarp >> 1;

    float4 areg[8];
    const float4* aa4 = reinterpret_cast<const float4*>(aa);
    {
        const int off = role ? 32 : 0;
#pragma unroll
        for (int i = 0; i < 8; i++)
            areg[i] = __ldg(&aa4[i * 64 + off + lane]);
    }

    const bool b16 = (lane & 16) != 0;
    const bool b8  = (lane & 8)  != 0;
    const bool b4  = (lane & 4)  != 0;
    const int  v   = (lane >> 2) & 7;
    const int  sub = lane & 3;

    const float4* x4 = reinterpret_cast<const float4*>(x);

    int node = wnode0;
    float4 xvA, xvB;
    bool hasA = (node < n_nodes);
    bool hasB = (node + nstep < n_nodes);
    if (hasA) xvA = __ldg(&x4[(size_t)node * 32 + lane]);
    if (hasB) xvB = __ldg(&x4[(size_t)(node + nstep) * 32 + lane]);

    while (hasA) {
        const int nodeB = node + nstep;
        const int nnode = node + 2 * nstep;

        float4 xvA2, xvB2;
        const bool hasA2 = (nnode < n_nodes);
        const bool hasB2 = (nnode + nstep < n_nodes);
        if (hasA2) xvA2 = __ldg(&x4[(size_t)nnode * 32 + lane]);
        if (hasB2) xvB2 = __ldg(&x4[(size_t)(nnode + nstep) * 32 + lane]);

        float accA[8], accB[8];
#pragma unroll
        for (int i = 0; i < 8; i++)
            accA[i] = xvA.x * areg[i].x + xvA.y * areg[i].y
                    + xvA.z * areg[i].z + xvA.w * areg[i].w;
        if (hasB) {
#pragma unroll
            for (int i = 0; i < 8; i++)
                accB[i] = xvB.x * areg[i].x + xvB.y * areg[i].y
                        + xvB.z * areg[i].z + xvB.w * areg[i].w;
        }

#pragma unroll
        for (int i = 0; i < 4; i++) {
            float gA = b16 ? accA[i] : accA[i + 4];
            float kA = b16 ? accA[i + 4] : accA[i];
            accA[i] = kA + __shfl_xor_sync(0xffffffffu, gA, 16);
        }
        if (hasB) {
#pragma unroll
            for (int i = 0; i < 4; i++) {
                float gB = b16 ? accB[i] : accB[i + 4];
                float kB = b16 ? accB[i + 4] : accB[i];
                accB[i] = kB + __shfl_xor_sync(0xffffffffu, gB, 16);
            }
        }
#pragma unroll
        for (int i = 0; i < 2; i++) {
            float gA = b8 ? accA[i] : accA[i + 2];
            float kA = b8 ? accA[i + 2] : accA[i];
            accA[i] = kA + __shfl_xor_sync(0xffffffffu, gA, 8);
        }
        if (hasB) {
#pragma unroll
            for (int i = 0; i < 2; i++) {
                float gB = b8 ? accB[i] : accB[i + 2];
                float kB = b8 ? accB[i + 2] : accB[i];
                accB[i] = kB + __shfl_xor_sync(0xffffffffu, gB, 8);
            }
        }
        {
            float gA = b4 ? accA[0] : accA[1];
            float kA = b4 ? accA[1] : accA[0];
            accA[0] = kA + __shfl_xor_sync(0xffffffffu, gA, 4);
        }
        if (hasB) {
            float gB = b4 ? accB[0] : accB[1];
            float kB = b4 ? accB[1] : accB[0];
            accB[0] = kB + __shfl_xor_sync(0xffffffffu, gB, 4);
        }
        accA[0] += __shfl_xor_sync(0xffffffffu, accA[0], 2);
        if (hasB) accB[0] += __shfl_xor_sync(0xffffffffu, accB[0], 2);
        accA[0] += __shfl_xor_sync(0xffffffffu, accA[0], 1);
        if (hasB) accB[0] += __shfl_xor_sync(0xffffffffu, accB[0], 1);

        if (role == 0) {
            if (sub == 0) {
                g_srcsum[(size_t)node * 16 + v] = accA[0];
                if (hasB) g_srcsum[(size_t)nodeB * 16 + v] = accB[0];
            } else if (sub == 1) {
                g_srcsum[(size_t)node * 16 + 8 + v] = 0.0f;
                if (hasB) g_srcsum[(size_t)nodeB * 16 + 8 + v] = 0.0f;
            }
        } else {
            if (sub == 0) {
                g_dst[(size_t)node * 8 + v] = accA[0];
                if (hasB) g_dst[(size_t)nodeB * 8 + v] = accB[0];
            }
        }

        node = nnode;
        hasA = hasA2; hasB = hasB2;
        xvA = xvA2;   xvB = xvB2;
    }
}

// ---------------------------------------------------------------------------
// Kernel 2: segment-sum of exp(e). Two threads per edge (R9 shape — this is
// the validated L1tex-queue sweet spot; do NOT batch more edges per thread).
// ---------------------------------------------------------------------------
__global__ void __launch_bounds__(256) sum_kernel(
    const int* __restrict__ row,
    const int* __restrict__ col,
    int n_edges)
{
    int t = blockIdx.x * blockDim.x + threadIdx.x;
    int e = t >> 1;
    int h = t & 1;
    if (e >= n_edges) return;
    int r = __ldg(row + e);
    int c = __ldg(col + e);

    const float4* s4 = reinterpret_cast<const float4*>(g_srcsum);
    const float4* d4 = reinterpret_cast<const float4*>(g_dst);
    float4 a = __ldg(&s4[(size_t)r * 4 + h]);
    float4 b = __ldg(&d4[(size_t)c * 2 + h]);

    float e0 = a.x + b.x, e1 = a.y + b.y, e2 = a.z + b.z, e3 = a.w + b.w;
    e0 = fmaxf(e0, ALPHA_F * e0); e1 = fmaxf(e1, ALPHA_F * e1);
    e2 = fmaxf(e2, ALPHA_F * e2); e3 = fmaxf(e3, ALPHA_F * e3);

    float x0 = __expf(e0), x1 = __expf(e1), x2 = __expf(e2), x3 = __expf(e3);

    float* dst = g_srcsum + (size_t)r * 16 + 8 + 4 * h;
    asm volatile("red.global.add.v4.f32 [%0], {%1,%2,%3,%4};"
                 :: "l"(dst), "f"(x0), "f"(x1), "f"(x2), "f"(x3)
                 : "memory");
}

// ---------------------------------------------------------------------------
// Kernel 3: a[head][e] = exp(e) * rcp(ssum[r][head] + EPS). Reciprocal fused
// (inv_kernel removed): 4 extra MUFU rcp per thread, hidden under the
// gather-bound wall; saves a kernel + 6.4MB of L2 RMW traffic.
// ---------------------------------------------------------------------------
__device__ __forceinline__ float frcp_fast(float v)
{
    float r;
    asm("rcp.approx.ftz.f32 %0, %1;" : "=f"(r) : "f"(v));
    return r;
}

__global__ void __launch_bounds__(256) out_kernel(
    const int* __restrict__ row,
    const int* __restrict__ col,
    float* __restrict__ out,
    int n_edges)
{
    int t = blockIdx.x * blockDim.x + threadIdx.x;
    int e = t >> 1;
    int h = t & 1;
    if (e >= n_edges) return;
    int r = __ldg(row + e);
    int c = __ldg(col + e);

    const float4* s4 = reinterpret_cast<const float4*>(g_srcsum);
    const float4* d4 = reinterpret_cast<const float4*>(g_dst);
    float4 a = __ldg(&s4[(size_t)r * 4 + h]);          // src scores
    float4 s = __ldg(&s4[(size_t)r * 4 + 2 + h]);      // raw ssum (same line)
    float4 b = __ldg(&d4[(size_t)c * 2 + h]);          // dst scores

    float e0 = a.x + b.x, e1 = a.y + b.y, e2 = a.z + b.z, e3 = a.w + b.w;
    e0 = fmaxf(e0, ALPHA_F * e0); e1 = fmaxf(e1, ALPHA_F * e1);
    e2 = fmaxf(e2, ALPHA_F * e2); e3 = fmaxf(e3, ALPHA_F * e3);

    float i0 = frcp_fast(s.x + EPS_F);
    float i1 = frcp_fast(s.y + EPS_F);
    float i2 = frcp_fast(s.z + EPS_F);
    float i3 = frcp_fast(s.w + EPS_F);

    size_t E = (size_t)n_edges;
    float* o = out + (size_t)(4 * h) * E + e;
    o[0 * E] = __expf(e0) * i0;
    o[1 * E] = __expf(e1) * i1;
    o[2 * E] = __expf(e2) * i2;
    o[3 * E] = __expf(e3) * i3;
}

extern "C" void kernel_launch(void* const* d_in, const int* in_sizes, int n_in,
                              void* d_out, int out_size)
{
    const float* x   = (const float*)d_in[0];
    const int*   row = (const int*)  d_in[1];
    const int*   col = (const int*)  d_in[2];
    const float* aa  = (const float*)d_in[3];
    float* out = (float*)d_out;

    int n_nodes = in_sizes[0] / FDIM;   // 100000
    int n_edges = in_sizes[1];          // 1600000

    scores_kernel<<<592, 256>>>(x, aa, n_nodes);

    int nthreads = 2 * n_edges;
    sum_kernel<<<(nthreads + 255) / 256, 256>>>(row, col, n_edges);
    out_kernel<<<(nthreads + 255) / 256, 256>>>(row, col, out, n_edges);
}

// round 12
// speedup vs baseline: 1.5682x; 1.5682x over previous
#include <cuda_runtime.h>
#include <cuda_bf16.h>
#include <cstdint>

#define N_NODES 100000
#define N_EDGES 1600000
#define FDIM    128
#define HEADS   8
#define EPS_F   1e-12f
#define ALPHA_F 0.2f

// Static device scratch (no runtime allocation).
// g_srcsum[n*16 + j] : j<8 -> s_src[n][j] ; j>=8 -> ssum[n][j-8] (raw sums).
//                      64B row per node: src scores + sums share a line.
// g_dst[n*8 + j]     : s_dst[n][j] (32B row).
__device__ __align__(128) float g_srcsum[N_NODES * 16];
__device__ __align__(128) float g_dst[N_NODES * 8];

// ---------------------------------------------------------------------------
// Kernel 1: per-node scores (R9 variant — two warps per node role-split,
// two nodes per iteration for MLP=2, NO deeper pipelining: the R10 prefetch
// version pushed regs to 80 and cost a residency wave).
// Grid sized to 444 = 3 blocks/SM x 148 SMs -> one clean wave.
// ---------------------------------------------------------------------------
__global__ void __launch_bounds__(256) scores_kernel(
    const float* __restrict__ x,
    const float* __restrict__ aa,
    int n_nodes)
{
    const int lane  = threadIdx.x & 31;
    const int gwarp = (blockIdx.x * blockDim.x + threadIdx.x) >> 5;
    const int nwarp = (gridDim.x * blockDim.x) >> 5;
    const int role  = gwarp & 1;            // 0: src rows, 1: dst rows
    const int wnode0 = gwarp >> 1;          // first node for this warp
    const int nstep  = nwarp >> 1;          // node stride

    float4 areg[8];
    const float4* aa4 = reinterpret_cast<const float4*>(aa);
    {
        const int off = role ? 32 : 0;
#pragma unroll
        for (int i = 0; i < 8; i++)
            areg[i] = __ldg(&aa4[i * 64 + off + lane]);
    }

    const bool b16 = (lane & 16) != 0;
    const bool b8  = (lane & 8)  != 0;
    const bool b4  = (lane & 4)  != 0;
    const int  v   = (lane >> 2) & 7;       // value index this lane ends with
    const int  sub = lane & 3;              // sub-lane within value group

    const float4* x4 = reinterpret_cast<const float4*>(x);

    for (int node = wnode0; node < n_nodes; node += 2 * nstep) {
        const int nodeB = node + nstep;
        const bool hasB = (nodeB < n_nodes);

        // Issue both independent loads first (MLP=2).
        float4 xvA = __ldg(&x4[(size_t)node * 32 + lane]);
        float4 xvB;
        if (hasB) xvB = __ldg(&x4[(size_t)nodeB * 32 + lane]);

        float accA[8], accB[8];
#pragma unroll
        for (int i = 0; i < 8; i++)
            accA[i] = xvA.x * areg[i].x + xvA.y * areg[i].y
                    + xvA.z * areg[i].z + xvA.w * areg[i].w;
        if (hasB) {
#pragma unroll
            for (int i = 0; i < 8; i++)
                accB[i] = xvB.x * areg[i].x + xvB.y * areg[i].y
                        + xvB.z * areg[i].z + xvB.w * areg[i].w;
        }

#pragma unroll
        for (int i = 0; i < 4; i++) {
            float gA = b16 ? accA[i] : accA[i + 4];
            float kA = b16 ? accA[i + 4] : accA[i];
            accA[i] = kA + __shfl_xor_sync(0xffffffffu, gA, 16);
        }
        if (hasB) {
#pragma unroll
            for (int i = 0; i < 4; i++) {
                float gB = b16 ? accB[i] : accB[i + 4];
                float kB = b16 ? accB[i + 4] : accB[i];
                accB[i] = kB + __shfl_xor_sync(0xffffffffu, gB, 16);
            }
        }
#pragma unroll
        for (int i = 0; i < 2; i++) {
            float gA = b8 ? accA[i] : accA[i + 2];
            float kA = b8 ? accA[i + 2] : accA[i];
            accA[i] = kA + __shfl_xor_sync(0xffffffffu, gA, 8);
        }
        if (hasB) {
#pragma unroll
            for (int i = 0; i < 2; i++) {
                float gB = b8 ? accB[i] : accB[i + 2];
                float kB = b8 ? accB[i + 2] : accB[i];
                accB[i] = kB + __shfl_xor_sync(0xffffffffu, gB, 8);
            }
        }
        {
            float gA = b4 ? accA[0] : accA[1];
            float kA = b4 ? accA[1] : accA[0];
            accA[0] = kA + __shfl_xor_sync(0xffffffffu, gA, 4);
        }
        if (hasB) {
            float gB = b4 ? accB[0] : accB[1];
            float kB = b4 ? accB[1] : accB[0];
            accB[0] = kB + __shfl_xor_sync(0xffffffffu, gB, 4);
        }
        accA[0] += __shfl_xor_sync(0xffffffffu, accA[0], 2);
        if (hasB) accB[0] += __shfl_xor_sync(0xffffffffu, accB[0], 2);
        accA[0] += __shfl_xor_sync(0xffffffffu, accA[0], 1);
        if (hasB) accB[0] += __shfl_xor_sync(0xffffffffu, accB[0], 1);

        if (role == 0) {
            if (sub == 0) {
                g_srcsum[(size_t)node * 16 + v] = accA[0];
                if (hasB) g_srcsum[(size_t)nodeB * 16 + v] = accB[0];
            } else if (sub == 1) {
                g_srcsum[(size_t)node * 16 + 8 + v] = 0.0f;
                if (hasB) g_srcsum[(size_t)nodeB * 16 + 8 + v] = 0.0f;
            }
        } else {
            if (sub == 0) {
                g_dst[(size_t)node * 8 + v] = accA[0];
                if (hasB) g_dst[(size_t)nodeB * 8 + v] = accB[0];
            }
        }
    }
}

// ---------------------------------------------------------------------------
// Kernel 2: segment-sum of exp(e). Two threads per edge, one red.v4 each
// (validated L1tex-queue sweet spot — do not batch more edges per thread).
// ---------------------------------------------------------------------------
__global__ void __launch_bounds__(256) sum_kernel(
    const int* __restrict__ row,
    const int* __restrict__ col,
    int n_edges)
{
    int t = blockIdx.x * blockDim.x + threadIdx.x;
    int e = t >> 1;
    int h = t & 1;
    if (e >= n_edges) return;
    int r = __ldg(row + e);
    int c = __ldg(col + e);

    const float4* s4 = reinterpret_cast<const float4*>(g_srcsum);
    const float4* d4 = reinterpret_cast<const float4*>(g_dst);
    float4 a = __ldg(&s4[(size_t)r * 4 + h]);
    float4 b = __ldg(&d4[(size_t)c * 2 + h]);

    float e0 = a.x + b.x, e1 = a.y + b.y, e2 = a.z + b.z, e3 = a.w + b.w;
    e0 = fmaxf(e0, ALPHA_F * e0); e1 = fmaxf(e1, ALPHA_F * e1);
    e2 = fmaxf(e2, ALPHA_F * e2); e3 = fmaxf(e3, ALPHA_F * e3);

    float x0 = __expf(e0), x1 = __expf(e1), x2 = __expf(e2), x3 = __expf(e3);

    float* dst = g_srcsum + (size_t)r * 16 + 8 + 4 * h;
    asm volatile("red.global.add.v4.f32 [%0], {%1,%2,%3,%4};"
                 :: "l"(dst), "f"(x0), "f"(x1), "f"(x2), "f"(x3)
                 : "memory");
}

// ---------------------------------------------------------------------------
// Kernel 3: a[head][e] = exp(e) * rcp(ssum[r][head] + EPS). Reciprocal fused
// (no separate inv kernel): 4 MUFU rcp per thread hidden under the gather
// wall; saves one launch + 6.4MB of L2 read-modify-write.
// ---------------------------------------------------------------------------
__device__ __forceinline__ float frcp_fast(float v)
{
    float r;
    asm("rcp.approx.ftz.f32 %0, %1;" : "=f"(r) : "f"(v));
    return r;
}

__global__ void __launch_bounds__(256) out_kernel(
    const int* __restrict__ row,
    const int* __restrict__ col,
    float* __restrict__ out,
    int n_edges)
{
    int t = blockIdx.x * blockDim.x + threadIdx.x;
    int e = t >> 1;
    int h = t & 1;
    if (e >= n_edges) return;
    int r = __ldg(row + e);
    int c = __ldg(col + e);

    const float4* s4 = reinterpret_cast<const float4*>(g_srcsum);
    const float4* d4 = reinterpret_cast<const float4*>(g_dst);
    float4 a = __ldg(&s4[(size_t)r * 4 + h]);          // src scores
    float4 s = __ldg(&s4[(size_t)r * 4 + 2 + h]);      // raw ssum (same line)
    float4 b = __ldg(&d4[(size_t)c * 2 + h]);          // dst scores

    float e0 = a.x + b.x, e1 = a.y + b.y, e2 = a.z + b.z, e3 = a.w + b.w;
    e0 = fmaxf(e0, ALPHA_F * e0); e1 = fmaxf(e1, ALPHA_F * e1);
    e2 = fmaxf(e2, ALPHA_F * e2); e3 = fmaxf(e3, ALPHA_F * e3);

    float i0 = frcp_fast(s.x + EPS_F);
    float i1 = frcp_fast(s.y + EPS_F);
    float i2 = frcp_fast(s.z + EPS_F);
    float i3 = frcp_fast(s.w + EPS_F);

    size_t E = (size_t)n_edges;
    float* o = out + (size_t)(4 * h) * E + e;
    o[0 * E] = __expf(e0) * i0;
    o[1 * E] = __expf(e1) * i1;
    o[2 * E] = __expf(e2) * i2;
    o[3 * E] = __expf(e3) * i3;
}

extern "C" void kernel_launch(void* const* d_in, const int* in_sizes, int n_in,
                              void* d_out, int out_size)
{
    const float* x   = (const float*)d_in[0];
    const int*   row = (const int*)  d_in[1];
    const int*   col = (const int*)  d_in[2];
    const float* aa  = (const float*)d_in[3];
    float* out = (float*)d_out;

    int n_nodes = in_sizes[0] / FDIM;   // 100000
    int n_edges = in_sizes[1];          // 1600000

    // 444 = 3 blocks/SM x 148 SMs: single full wave at this kernel's
    // register-limited residency (3 blocks/SM).
    scores_kernel<<<444, 256>>>(x, aa, n_nodes);

    int nthreads = 2 * n_edges;
    sum_kernel<<<(nthreads + 255) / 256, 256>>>(row, col, n_edges);
    out_kernel<<<(nthreads + 255) / 256, 256>>>(row, col, out, n_edges);
}

// round 13
// speedup vs baseline: 1.7452x; 1.1129x over previous
#include <cuda_runtime.h>
#include <cuda_bf16.h>
#include <cstdint>

#define N_NODES 100000
#define N_EDGES 1600000
#define FDIM    128
#define HEADS   8
#define EPS_F   1e-12f
#define ALPHA_F 0.2f

// Static device scratch (no runtime allocation).
// g_srcsum[n*16 + j] : j<8 -> s_src[n][j] ; j>=8 -> ssum[n][j-8] (raw sums).
//                      64B row per node: src scores + sums share a line.
// g_dst[n*8 + j]     : s_dst[n][j] (32B row).
__device__ __align__(128) float g_srcsum[N_NODES * 16];
__device__ __align__(128) float g_dst[N_NODES * 8];

// ---------------------------------------------------------------------------
// Value-splitting reduction over 8 accumulators (compile-time indices).
// After: all 4 lanes of group (lane>>2) hold full dot for v=(lane>>2)&7.
// ---------------------------------------------------------------------------
__device__ __forceinline__ float reduce8(float acc[8], bool b16, bool b8, bool b4)
{
#pragma unroll
    for (int i = 0; i < 4; i++) {
        float g = b16 ? acc[i] : acc[i + 4];
        float k = b16 ? acc[i + 4] : acc[i];
        acc[i] = k + __shfl_xor_sync(0xffffffffu, g, 16);
    }
#pragma unroll
    for (int i = 0; i < 2; i++) {
        float g = b8 ? acc[i] : acc[i + 2];
        float k = b8 ? acc[i + 2] : acc[i];
        acc[i] = k + __shfl_xor_sync(0xffffffffu, g, 8);
    }
    {
        float g = b4 ? acc[0] : acc[1];
        float k = b4 ? acc[1] : acc[0];
        acc[0] = k + __shfl_xor_sync(0xffffffffu, g, 4);
    }
    acc[0] += __shfl_xor_sync(0xffffffffu, acc[0], 2);
    acc[0] += __shfl_xor_sync(0xffffffffu, acc[0], 1);
    return acc[0];
}

// ---------------------------------------------------------------------------
// Kernel 1: per-node scores. Two warps per node (role 0 = src rows, role 1 =
// dst rows), two nodes per iteration (MLP=2 on the coalesced x stream).
// Main loop is UNPREDICATED (both nodes guaranteed in range); one explicit
// single-node tail handles the ragged end. Grid 592 = 4 blocks/SM (64 regs).
// ---------------------------------------------------------------------------
__global__ void __launch_bounds__(256) scores_kernel(
    const float* __restrict__ x,
    const float* __restrict__ aa,
    int n_nodes)
{
    const int lane  = threadIdx.x & 31;
    const int gwarp = (blockIdx.x * blockDim.x + threadIdx.x) >> 5;
    const int nwarp = (gridDim.x * blockDim.x) >> 5;
    const int role  = gwarp & 1;            // 0: src rows, 1: dst rows
    const int wnode0 = gwarp >> 1;
    const int nstep  = nwarp >> 1;

    float4 areg[8];
    const float4* aa4 = reinterpret_cast<const float4*>(aa);
    {
        const int off = role ? 32 : 0;
#pragma unroll
        for (int i = 0; i < 8; i++)
            areg[i] = __ldg(&aa4[i * 64 + off + lane]);
    }

    const bool b16 = (lane & 16) != 0;
    const bool b8  = (lane & 8)  != 0;
    const bool b4  = (lane & 4)  != 0;
    const int  v   = (lane >> 2) & 7;
    const int  sub = lane & 3;

    const float4* x4 = reinterpret_cast<const float4*>(x);

    int node = wnode0;
    // Main loop: both node and node+nstep strictly in range -> no predication.
    for (; node + nstep < n_nodes; node += 2 * nstep) {
        const int nodeB = node + nstep;

        float4 xvA = __ldg(&x4[(size_t)node * 32 + lane]);
        float4 xvB = __ldg(&x4[(size_t)nodeB * 32 + lane]);

        float accA[8], accB[8];
#pragma unroll
        for (int i = 0; i < 8; i++)
            accA[i] = xvA.x * areg[i].x + xvA.y * areg[i].y
                    + xvA.z * areg[i].z + xvA.w * areg[i].w;
#pragma unroll
        for (int i = 0; i < 8; i++)
            accB[i] = xvB.x * areg[i].x + xvB.y * areg[i].y
                    + xvB.z * areg[i].z + xvB.w * areg[i].w;

        float rA = reduce8(accA, b16, b8, b4);
        float rB = reduce8(accB, b16, b8, b4);

        if (role == 0) {
            if (sub == 0) {
                g_srcsum[(size_t)node * 16 + v]  = rA;
                g_srcsum[(size_t)nodeB * 16 + v] = rB;
            } else if (sub == 1) {
                g_srcsum[(size_t)node * 16 + 8 + v]  = 0.0f;
                g_srcsum[(size_t)nodeB * 16 + 8 + v] = 0.0f;
            }
        } else {
            if (sub == 0) {
                g_dst[(size_t)node * 8 + v]  = rA;
                g_dst[(size_t)nodeB * 8 + v] = rB;
            }
        }
    }
    // Tail: at most one lone node.
    if (node < n_nodes) {
        float4 xvA = __ldg(&x4[(size_t)node * 32 + lane]);
        float accA[8];
#pragma unroll
        for (int i = 0; i < 8; i++)
            accA[i] = xvA.x * areg[i].x + xvA.y * areg[i].y
                    + xvA.z * areg[i].z + xvA.w * areg[i].w;
        float rA = reduce8(accA, b16, b8, b4);
        if (role == 0) {
            if (sub == 0)      g_srcsum[(size_t)node * 16 + v]     = rA;
            else if (sub == 1) g_srcsum[(size_t)node * 16 + 8 + v] = 0.0f;
        } else if (sub == 0) {
            g_dst[(size_t)node * 8 + v] = rA;
        }
    }
}

// ---------------------------------------------------------------------------
// Kernel 2: segment-sum of exp(e). Two threads per edge, one red.v4 each
// (validated L1tex-queue sweet spot — do not batch more edges per thread).
// ---------------------------------------------------------------------------
__global__ void __launch_bounds__(256) sum_kernel(
    const int* __restrict__ row,
    const int* __restrict__ col,
    int n_edges)
{
    int t = blockIdx.x * blockDim.x + threadIdx.x;
    int e = t >> 1;
    int h = t & 1;
    if (e >= n_edges) return;
    int r = __ldg(row + e);
    int c = __ldg(col + e);

    const float4* s4 = reinterpret_cast<const float4*>(g_srcsum);
    const float4* d4 = reinterpret_cast<const float4*>(g_dst);
    float4 a = __ldg(&s4[(size_t)r * 4 + h]);
    float4 b = __ldg(&d4[(size_t)c * 2 + h]);

    float e0 = a.x + b.x, e1 = a.y + b.y, e2 = a.z + b.z, e3 = a.w + b.w;
    e0 = fmaxf(e0, ALPHA_F * e0); e1 = fmaxf(e1, ALPHA_F * e1);
    e2 = fmaxf(e2, ALPHA_F * e2); e3 = fmaxf(e3, ALPHA_F * e3);

    float x0 = __expf(e0), x1 = __expf(e1), x2 = __expf(e2), x3 = __expf(e3);

    float* dst = g_srcsum + (size_t)r * 16 + 8 + 4 * h;
    asm volatile("red.global.add.v4.f32 [%0], {%1,%2,%3,%4};"
                 :: "l"(dst), "f"(x0), "f"(x1), "f"(x2), "f"(x3)
                 : "memory");
}

// ---------------------------------------------------------------------------
// Kernel 3: a[head][e] = exp(e) * rcp(ssum[r][head] + EPS). Reciprocal fused.
// ---------------------------------------------------------------------------
__device__ __forceinline__ float frcp_fast(float v)
{
    float r;
    asm("rcp.approx.ftz.f32 %0, %1;" : "=f"(r) : "f"(v));
    return r;
}

__global__ void __launch_bounds__(256) out_kernel(
    const int* __restrict__ row,
    const int* __restrict__ col,
    float* __restrict__ out,
    int n_edges)
{
    int t = blockIdx.x * blockDim.x + threadIdx.x;
    int e = t >> 1;
    int h = t & 1;
    if (e >= n_edges) return;
    int r = __ldg(row + e);
    int c = __ldg(col + e);

    const float4* s4 = reinterpret_cast<const float4*>(g_srcsum);
    const float4* d4 = reinterpret_cast<const float4*>(g_dst);
    float4 a = __ldg(&s4[(size_t)r * 4 + h]);          // src scores
    float4 s = __ldg(&s4[(size_t)r * 4 + 2 + h]);      // raw ssum (same line)
    float4 b = __ldg(&d4[(size_t)c * 2 + h]);          // dst scores

    float e0 = a.x + b.x, e1 = a.y + b.y, e2 = a.z + b.z, e3 = a.w + b.w;
    e0 = fmaxf(e0, ALPHA_F * e0); e1 = fmaxf(e1, ALPHA_F * e1);
    e2 = fmaxf(e2, ALPHA_F * e2); e3 = fmaxf(e3, ALPHA_F * e3);

    float i0 = frcp_fast(s.x + EPS_F);
    float i1 = frcp_fast(s.y + EPS_F);
    float i2 = frcp_fast(s.z + EPS_F);
    float i3 = frcp_fast(s.w + EPS_F);

    size_t E = (size_t)n_edges;
    float* o = out + (size_t)(4 * h) * E + e;
    o[0 * E] = __expf(e0) * i0;
    o[1 * E] = __expf(e1) * i1;
    o[2 * E] = __expf(e2) * i2;
    o[3 * E] = __expf(e3) * i3;
}

extern "C" void kernel_launch(void* const* d_in, const int* in_sizes, int n_in,
                              void* d_out, int out_size)
{
    const float* x   = (const float*)d_in[0];
    const int*   row = (const int*)  d_in[1];
    const int*   col = (const int*)  d_in[2];
    const float* aa  = (const float*)d_in[3];
    float* out = (float*)d_out;

    int n_nodes = in_sizes[0] / FDIM;   // 100000
    int n_edges = in_sizes[1];          // 1600000

    // 592 = 4 blocks/SM x 148 SMs at 64 regs/thread (full residency).
    scores_kernel<<<592, 256>>>(x, aa, n_nodes);

    int nthreads = 2 * n_edges;
    sum_kernel<<<(nthreads + 255) / 256, 256>>>(row, col, n_edges);
    out_kernel<<<(nthreads + 255) / 256, 256>>>(row, col, out, n_edges);
}

// round 14
// speedup vs baseline: 1.8031x; 1.0332x over previous
#include <cuda_runtime.h>
#include <cuda_bf16.h>
#include <cstdint>

#define N_NODES 100000
#define N_EDGES 1600000
#define FDIM    128
#define HEADS   8
#define EPS_F   1e-12f
#define ALPHA_F 0.2f

// Static device scratch (no runtime allocation).
// g_srcsum[n*16 + j] : j<8 -> s_src[n][j] ; j>=8 -> ssum[n][j-8] (raw sums).
//                      64B row per node: src scores + sums share a line.
// g_dst[n*8 + j]     : s_dst[n][j] (32B row).
__device__ __align__(128) float g_srcsum[N_NODES * 16];
__device__ __align__(128) float g_dst[N_NODES * 8];

// ---------------------------------------------------------------------------
// Select-free value-splitting reduction. Precondition: lane l's slot s holds
// the partial dot of row (s ^ v) where v = (lane>>2)&7 (arranged at areg load
// time). Then every round's keep is slot i and give is slot i+half — the
// partner's give is exactly the row this lane keeps:
//   round 16: partner v^4, slot i+4 -> row (i+4)^(v^4) = i^v  (match)
//   round  8: partner v^2, slot i+2 -> row (i+2)^(v^2) = i^v  (match)
//   round  4: partner v^1, slot 1   -> row 1^(v^1)     = v    (match)
// After round 4, acc[0] = partial of row v over this lane's 4 features;
// rounds 2,1 sum the 4 sub-lanes. NO selects anywhere.
// ---------------------------------------------------------------------------
__device__ __forceinline__ float reduce8_perm(float acc[8])
{
#pragma unroll
    for (int i = 0; i < 4; i++)
        acc[i] += __shfl_xor_sync(0xffffffffu, acc[i + 4], 16);
#pragma unroll
    for (int i = 0; i < 2; i++)
        acc[i] += __shfl_xor_sync(0xffffffffu, acc[i + 2], 8);
    acc[0] += __shfl_xor_sync(0xffffffffu, acc[1], 4);
    acc[0] += __shfl_xor_sync(0xffffffffu, acc[0], 2);
    acc[0] += __shfl_xor_sync(0xffffffffu, acc[0], 1);
    return acc[0];
}

// ---------------------------------------------------------------------------
// Kernel 1: per-node scores. Two warps per node (role 0 = src, role 1 = dst),
// two nodes per iteration (MLP=2), unpredicated main loop + explicit tail.
// areg slot s holds row (s ^ v) — enables the select-free reduction above.
// Grid 592 = 4 blocks/SM at 64 regs (validated full residency).
// ---------------------------------------------------------------------------
__global__ void __launch_bounds__(256) scores_kernel(
    const float* __restrict__ x,
    const float* __restrict__ aa,
    int n_nodes)
{
    const int lane  = threadIdx.x & 31;
    const int gwarp = (blockIdx.x * blockDim.x + threadIdx.x) >> 5;
    const int nwarp = (gridDim.x * blockDim.x) >> 5;
    const int role  = gwarp & 1;            // 0: src rows, 1: dst rows
    const int wnode0 = gwarp >> 1;
    const int nstep  = nwarp >> 1;

    const int v   = (lane >> 2) & 7;        // value this lane ends holding
    const int sub = lane & 3;               // sub-lane within value group

    // areg[s] = aa row (s ^ v) of this role's half, features [4*lane&...].
    float4 areg[8];
    const float4* aa4 = reinterpret_cast<const float4*>(aa);
    {
        const int off = role ? 32 : 0;
#pragma unroll
        for (int s = 0; s < 8; s++)
            areg[s] = __ldg(&aa4[(s ^ v) * 64 + off + lane]);
    }

    const float4* x4 = reinterpret_cast<const float4*>(x);

    int node = wnode0;
    for (; node + nstep < n_nodes; node += 2 * nstep) {
        const int nodeB = node + nstep;

        float4 xvA = __ldg(&x4[(size_t)node * 32 + lane]);
        float4 xvB = __ldg(&x4[(size_t)nodeB * 32 + lane]);

        float accA[8], accB[8];
#pragma unroll
        for (int i = 0; i < 8; i++)
            accA[i] = xvA.x * areg[i].x + xvA.y * areg[i].y
                    + xvA.z * areg[i].z + xvA.w * areg[i].w;
#pragma unroll
        for (int i = 0; i < 8; i++)
            accB[i] = xvB.x * areg[i].x + xvB.y * areg[i].y
                    + xvB.z * areg[i].z + xvB.w * areg[i].w;

        float rA = reduce8_perm(accA);
        float rB = reduce8_perm(accB);

        if (role == 0) {
            if (sub == 0) {
                g_srcsum[(size_t)node * 16 + v]  = rA;
                g_srcsum[(size_t)nodeB * 16 + v] = rB;
            } else if (sub == 1) {
                g_srcsum[(size_t)node * 16 + 8 + v]  = 0.0f;
                g_srcsum[(size_t)nodeB * 16 + 8 + v] = 0.0f;
            }
        } else {
            if (sub == 0) {
                g_dst[(size_t)node * 8 + v]  = rA;
                g_dst[(size_t)nodeB * 8 + v] = rB;
            }
        }
    }
    if (node < n_nodes) {
        float4 xvA = __ldg(&x4[(size_t)node * 32 + lane]);
        float accA[8];
#pragma unroll
        for (int i = 0; i < 8; i++)
            accA[i] = xvA.x * areg[i].x + xvA.y * areg[i].y
                    + xvA.z * areg[i].z + xvA.w * areg[i].w;
        float rA = reduce8_perm(accA);
        if (role == 0) {
            if (sub == 0)      g_srcsum[(size_t)node * 16 + v]     = rA;
            else if (sub == 1) g_srcsum[(size_t)node * 16 + 8 + v] = 0.0f;
        } else if (sub == 0) {
            g_dst[(size_t)node * 8 + v] = rA;
        }
    }
}

// ---------------------------------------------------------------------------
// Kernel 2: segment-sum of exp(e). Two threads per edge, one red.v4 each
// (validated L1tex-queue sweet spot — do not batch more edges per thread).
// ---------------------------------------------------------------------------
__global__ void __launch_bounds__(256) sum_kernel(
    const int* __restrict__ row,
    const int* __restrict__ col,
    int n_edges)
{
    int t = blockIdx.x * blockDim.x + threadIdx.x;
    int e = t >> 1;
    int h = t & 1;
    if (e >= n_edges) return;
    int r = __ldg(row + e);
    int c = __ldg(col + e);

    const float4* s4 = reinterpret_cast<const float4*>(g_srcsum);
    const float4* d4 = reinterpret_cast<const float4*>(g_dst);
    float4 a = __ldg(&s4[(size_t)r * 4 + h]);
    float4 b = __ldg(&d4[(size_t)c * 2 + h]);

    float e0 = a.x + b.x, e1 = a.y + b.y, e2 = a.z + b.z, e3 = a.w + b.w;
    e0 = fmaxf(e0, ALPHA_F * e0); e1 = fmaxf(e1, ALPHA_F * e1);
    e2 = fmaxf(e2, ALPHA_F * e2); e3 = fmaxf(e3, ALPHA_F * e3);

    float x0 = __expf(e0), x1 = __expf(e1), x2 = __expf(e2), x3 = __expf(e3);

    float* dst = g_srcsum + (size_t)r * 16 + 8 + 4 * h;
    asm volatile("red.global.add.v4.f32 [%0], {%1,%2,%3,%4};"
                 :: "l"(dst), "f"(x0), "f"(x1), "f"(x2), "f"(x3)
                 : "memory");
}

// ---------------------------------------------------------------------------
// Kernel 3: a[head][e] = exp(e) * rcp(ssum[r][head] + EPS). Reciprocal fused.
// ---------------------------------------------------------------------------
__device__ __forceinline__ float frcp_fast(float v)
{
    float r;
    asm("rcp.approx.ftz.f32 %0, %1;" : "=f"(r) : "f"(v));
    return r;
}

__global__ void __launch_bounds__(256) out_kernel(
    const int* __restrict__ row,
    const int* __restrict__ col,
    float* __restrict__ out,
    int n_edges)
{
    int t = blockIdx.x * blockDim.x + threadIdx.x;
    int e = t >> 1;
    int h = t & 1;
    if (e >= n_edges) return;
    int r = __ldg(row + e);
    int c = __ldg(col + e);

    const float4* s4 = reinterpret_cast<const float4*>(g_srcsum);
    const float4* d4 = reinterpret_cast<const float4*>(g_dst);
    float4 a = __ldg(&s4[(size_t)r * 4 + h]);          // src scores
    float4 s = __ldg(&s4[(size_t)r * 4 + 2 + h]);      // raw ssum (same line)
    float4 b = __ldg(&d4[(size_t)c * 2 + h]);          // dst scores

    float e0 = a.x + b.x, e1 = a.y + b.y, e2 = a.z + b.z, e3 = a.w + b.w;
    e0 = fmaxf(e0, ALPHA_F * e0); e1 = fmaxf(e1, ALPHA_F * e1);
    e2 = fmaxf(e2, ALPHA_F * e2); e3 = fmaxf(e3, ALPHA_F * e3);

    float i0 = frcp_fast(s.x + EPS_F);
    float i1 = frcp_fast(s.y + EPS_F);
    float i2 = frcp_fast(s.z + EPS_F);
    float i3 = frcp_fast(s.w + EPS_F);

    size_t E = (size_t)n_edges;
    float* o = out + (size_t)(4 * h) * E + e;
    o[0 * E] = __expf(e0) * i0;
    o[1 * E] = __expf(e1) * i1;
    o[2 * E] = __expf(e2) * i2;
    o[3 * E] = __expf(e3) * i3;
}

extern "C" void kernel_launch(void* const* d_in, const int* in_sizes, int n_in,
                              void* d_out, int out_size)
{
    const float* x   = (const float*)d_in[0];
    const int*   row = (const int*)  d_in[1];
    const int*   col = (const int*)  d_in[2];
    const float* aa  = (const float*)d_in[3];
    float* out = (float*)d_out;

    int n_nodes = in_sizes[0] / FDIM;   // 100000
    int n_edges = in_sizes[1];          // 1600000

    // 592 = 4 blocks/SM x 148 SMs at 64 regs/thread (full residency).
    scores_kernel<<<592, 256>>>(x, aa, n_nodes);

    int nthreads = 2 * n_edges;
    sum_kernel<<<(nthreads + 255) / 256, 256>>>(row, col, n_edges);
    out_kernel<<<(nthreads + 255) / 256, 256>>>(row, col, out, n_edges);
}

// round 15
// speedup vs baseline: 1.8331x; 1.0166x over previous
#include <cuda_runtime.h>
#include <cuda_bf16.h>
#include <cstdint>

#define N_NODES 100000
#define N_EDGES 1600000
#define FDIM    128
#define HEADS   8
#define EPS_F   1e-12f
#define ALPHA_F 0.2f

typedef unsigned long long u64;

// Static device scratch (no runtime allocation).
// g_srcsum[n*16 + j] : j<8 -> s_src[n][j] ; j>=8 -> ssum[n][j-8] (raw sums).
//                      64B row per node: src scores + sums share a line.
// g_dst[n*8 + j]     : s_dst[n][j] (32B row).
__device__ __align__(128) float g_srcsum[N_NODES * 16];
__device__ __align__(128) float g_dst[N_NODES * 8];

// ---- f32x2 packed helpers (FFMA2 is only reachable via PTX) ---------------
__device__ __forceinline__ u64 pack2(float lo, float hi)
{
    u64 r;
    asm("mov.b64 %0, {%1, %2};" : "=l"(r) : "f"(lo), "f"(hi));
    return r;
}
__device__ __forceinline__ void unpack2(float& lo, float& hi, u64 v)
{
    asm("mov.b64 {%0, %1}, %2;" : "=f"(lo), "=f"(hi) : "l"(v));
}
__device__ __forceinline__ u64 mul2(u64 a, u64 b)
{
    u64 d;
    asm("mul.rn.f32x2 %0, %1, %2;" : "=l"(d) : "l"(a), "l"(b));
    return d;
}
__device__ __forceinline__ u64 fma2(u64 a, u64 b, u64 c)
{
    u64 d;
    asm("fma.rn.f32x2 %0, %1, %2, %3;" : "=l"(d) : "l"(a), "l"(b), "l"(c));
    return d;
}

// ---------------------------------------------------------------------------
// Select-free value-splitting reduction (validated R14). Lane l's slot s
// holds the partial of row (s ^ v), v=(lane>>2)&7: every round's give is
// slot i+half and the received value is exactly the kept row's partial.
// ---------------------------------------------------------------------------
__device__ __forceinline__ float reduce8_perm(float acc[8])
{
#pragma unroll
    for (int i = 0; i < 4; i++)
        acc[i] += __shfl_xor_sync(0xffffffffu, acc[i + 4], 16);
#pragma unroll
    for (int i = 0; i < 2; i++)
        acc[i] += __shfl_xor_sync(0xffffffffu, acc[i + 2], 8);
    acc[0] += __shfl_xor_sync(0xffffffffu, acc[1], 4);
    acc[0] += __shfl_xor_sync(0xffffffffu, acc[0], 2);
    acc[0] += __shfl_xor_sync(0xffffffffu, acc[0], 1);
    return acc[0];
}

// Packed dot: accp[p] = sum_f aregp[p*4+f] * (xv.f, xv.f); then unpack.
__device__ __forceinline__ void dot8_packed(const u64 aregp[16], float4 xv,
                                            float acc[8])
{
    u64 xx = pack2(xv.x, xv.x);
    u64 xy = pack2(xv.y, xv.y);
    u64 xz = pack2(xv.z, xv.z);
    u64 xw = pack2(xv.w, xv.w);
#pragma unroll
    for (int p = 0; p < 4; p++) {
        u64 t = mul2(aregp[p * 4 + 0], xx);
        t = fma2(aregp[p * 4 + 1], xy, t);
        t = fma2(aregp[p * 4 + 2], xz, t);
        t = fma2(aregp[p * 4 + 3], xw, t);
        unpack2(acc[2 * p], acc[2 * p + 1], t);
    }
}

// ---------------------------------------------------------------------------
// Kernel 1: per-node scores. Two warps per node (role 0 = src, role 1 = dst),
// two nodes per iteration (MLP=2), unpredicated main loop + explicit tail.
// FFMA loop packed as f32x2 (16 FFMA2/node instead of 32 FFMA).
// launch_bounds(256,4) pins regs<=64 -> 4 blocks/SM residency guaranteed.
// ---------------------------------------------------------------------------
__global__ void __launch_bounds__(256, 4) scores_kernel(
    const float* __restrict__ x,
    const float* __restrict__ aa,
    int n_nodes)
{
    const int lane  = threadIdx.x & 31;
    const int gwarp = (blockIdx.x * blockDim.x + threadIdx.x) >> 5;
    const int nwarp = (gridDim.x * blockDim.x) >> 5;
    const int role  = gwarp & 1;            // 0: src rows, 1: dst rows
    const int wnode0 = gwarp >> 1;
    const int nstep  = nwarp >> 1;

    const int v   = (lane >> 2) & 7;        // value this lane ends holding
    const int sub = lane & 3;               // sub-lane within value group

    // aregp[p*4+f] = packed (row (2p)^v feature f, row (2p+1)^v feature f).
    u64 aregp[16];
    const float4* aa4 = reinterpret_cast<const float4*>(aa);
    {
        const int off = role ? 32 : 0;
#pragma unroll
        for (int p = 0; p < 4; p++) {
            float4 r0 = __ldg(&aa4[((2 * p)     ^ v) * 64 + off + lane]);
            float4 r1 = __ldg(&aa4[((2 * p + 1) ^ v) * 64 + off + lane]);
            aregp[p * 4 + 0] = pack2(r0.x, r1.x);
            aregp[p * 4 + 1] = pack2(r0.y, r1.y);
            aregp[p * 4 + 2] = pack2(r0.z, r1.z);
            aregp[p * 4 + 3] = pack2(r0.w, r1.w);
        }
    }

    const float4* x4 = reinterpret_cast<const float4*>(x);

    int node = wnode0;
    for (; node + nstep < n_nodes; node += 2 * nstep) {
        const int nodeB = node + nstep;

        float4 xvA = __ldg(&x4[(size_t)node * 32 + lane]);
        float4 xvB = __ldg(&x4[(size_t)nodeB * 32 + lane]);

        float accA[8], accB[8];
        dot8_packed(aregp, xvA, accA);
        dot8_packed(aregp, xvB, accB);

        float rA = reduce8_perm(accA);
        float rB = reduce8_perm(accB);

        if (role == 0) {
            if (sub == 0) {
                g_srcsum[(size_t)node * 16 + v]  = rA;
                g_srcsum[(size_t)nodeB * 16 + v] = rB;
            } else if (sub == 1) {
                g_srcsum[(size_t)node * 16 + 8 + v]  = 0.0f;
                g_srcsum[(size_t)nodeB * 16 + 8 + v] = 0.0f;
            }
        } else {
            if (sub == 0) {
                g_dst[(size_t)node * 8 + v]  = rA;
                g_dst[(size_t)nodeB * 8 + v] = rB;
            }
        }
    }
    if (node < n_nodes) {
        float4 xvA = __ldg(&x4[(size_t)node * 32 + lane]);
        float accA[8];
        dot8_packed(aregp, xvA, accA);
        float rA = reduce8_perm(accA);
        if (role == 0) {
            if (sub == 0)      g_srcsum[(size_t)node * 16 + v]     = rA;
            else if (sub == 1) g_srcsum[(size_t)node * 16 + 8 + v] = 0.0f;
        } else if (sub == 0) {
            g_dst[(size_t)node * 8 + v] = rA;
        }
    }
}

// ---------------------------------------------------------------------------
// Kernel 2: segment-sum of exp(e). Two threads per edge, one red.v4 each
// (validated L1tex-queue sweet spot — do not batch more edges per thread).
// ---------------------------------------------------------------------------
__global__ void __launch_bounds__(256) sum_kernel(
    const int* __restrict__ row,
    const int* __restrict__ col,
    int n_edges)
{
    int t = blockIdx.x * blockDim.x + threadIdx.x;
    int e = t >> 1;
    int h = t & 1;
    if (e >= n_edges) return;
    int r = __ldg(row + e);
    int c = __ldg(col + e);

    const float4* s4 = reinterpret_cast<const float4*>(g_srcsum);
    const float4* d4 = reinterpret_cast<const float4*>(g_dst);
    float4 a = __ldg(&s4[(size_t)r * 4 + h]);
    float4 b = __ldg(&d4[(size_t)c * 2 + h]);

    float e0 = a.x + b.x, e1 = a.y + b.y, e2 = a.z + b.z, e3 = a.w + b.w;
    e0 = fmaxf(e0, ALPHA_F * e0); e1 = fmaxf(e1, ALPHA_F * e1);
    e2 = fmaxf(e2, ALPHA_F * e2); e3 = fmaxf(e3, ALPHA_F * e3);

    float x0 = __expf(e0), x1 = __expf(e1), x2 = __expf(e2), x3 = __expf(e3);

    float* dst = g_srcsum + (size_t)r * 16 + 8 + 4 * h;
    asm volatile("red.global.add.v4.f32 [%0], {%1,%2,%3,%4};"
                 :: "l"(dst), "f"(x0), "f"(x1), "f"(x2), "f"(x3)
                 : "memory");
}

// ---------------------------------------------------------------------------
// Kernel 3: a[head][e] = exp(e) * rcp(ssum[r][head] + EPS). Reciprocal fused.
// ---------------------------------------------------------------------------
__device__ __forceinline__ float frcp_fast(float v)
{
    float r;
    asm("rcp.approx.ftz.f32 %0, %1;" : "=f"(r) : "f"(v));
    return r;
}

__global__ void __launch_bounds__(256) out_kernel(
    const int* __restrict__ row,
    const int* __restrict__ col,
    float* __restrict__ out,
    int n_edges)
{
    int t = blockIdx.x * blockDim.x + threadIdx.x;
    int e = t >> 1;
    int h = t & 1;
    if (e >= n_edges) return;
    int r = __ldg(row + e);
    int c = __ldg(col + e);

    const float4* s4 = reinterpret_cast<const float4*>(g_srcsum);
    const float4* d4 = reinterpret_cast<const float4*>(g_dst);
    float4 a = __ldg(&s4[(size_t)r * 4 + h]);          // src scores
    float4 s = __ldg(&s4[(size_t)r * 4 + 2 + h]);      // raw ssum (same line)
    float4 b = __ldg(&d4[(size_t)c * 2 + h]);          // dst scores

    float e0 = a.x + b.x, e1 = a.y + b.y, e2 = a.z + b.z, e3 = a.w + b.w;
    e0 = fmaxf(e0, ALPHA_F * e0); e1 = fmaxf(e1, ALPHA_F * e1);
    e2 = fmaxf(e2, ALPHA_F * e2); e3 = fmaxf(e3, ALPHA_F * e3);

    float i0 = frcp_fast(s.x + EPS_F);
    float i1 = frcp_fast(s.y + EPS_F);
    float i2 = frcp_fast(s.z + EPS_F);
    float i3 = frcp_fast(s.w + EPS_F);

    size_t E = (size_t)n_edges;
    float* o = out + (size_t)(4 * h) * E + e;
    o[0 * E] = __expf(e0) * i0;
    o[1 * E] = __expf(e1) * i1;
    o[2 * E] = __expf(e2) * i2;
    o[3 * E] = __expf(e3) * i3;
}

extern "C" void kernel_launch(void* const* d_in, const int* in_sizes, int n_in,
                              void* d_out, int out_size)
{
    const float* x   = (const float*)d_in[0];
    const int*   row = (const int*)  d_in[1];
    const int*   col = (const int*)  d_in[2];
    const float* aa  = (const float*)d_in[3];
    float* out = (float*)d_out;

    int n_nodes = in_sizes[0] / FDIM;   // 100000
    int n_edges = in_sizes[1];          // 1600000

    // 592 = 4 blocks/SM x 148 SMs (residency pinned by launch_bounds).
    scores_kernel<<<592, 256>>>(x, aa, n_nodes);

    int nthreads = 2 * n_edges;
    sum_kernel<<<(nthreads + 255) / 256, 256>>>(row, col, n_edges);
    out_kernel<<<(nthreads + 255) / 256, 256>>>(row, col, out, n_edges);
}

// round 16
// speedup vs baseline: 1.8849x; 1.0282x over previous
#include <cuda_runtime.h>
#include <cuda_bf16.h>
#include <cstdint>

#define N_NODES 100000
#define N_EDGES 1600000
#define FDIM    128
#define HEADS   8
#define EPS_F   1e-12f
#define ALPHA_F 0.2f

typedef unsigned long long u64;

// Static device scratch (no runtime allocation).
// g_srcsum[n*16 + j] : j<8 -> s_src[n][j] ; j>=8 -> ssum[n][j-8] (raw sums).
//                      64B row per node: src scores + sums share a line.
// g_dst[n*8 + j]     : s_dst[n][j] (32B row).
__device__ __align__(128) float g_srcsum[N_NODES * 16];
__device__ __align__(128) float g_dst[N_NODES * 8];

// ---- f32x2 packed helpers (FFMA2 is only reachable via PTX) ---------------
__device__ __forceinline__ u64 pack2(float lo, float hi)
{
    u64 r;
    asm("mov.b64 %0, {%1, %2};" : "=l"(r) : "f"(lo), "f"(hi));
    return r;
}
__device__ __forceinline__ void unpack2(float& lo, float& hi, u64 v)
{
    asm("mov.b64 {%0, %1}, %2;" : "=f"(lo), "=f"(hi) : "l"(v));
}
__device__ __forceinline__ u64 mul2(u64 a, u64 b)
{
    u64 d;
    asm("mul.rn.f32x2 %0, %1, %2;" : "=l"(d) : "l"(a), "l"(b));
    return d;
}
__device__ __forceinline__ u64 fma2(u64 a, u64 b, u64 c)
{
    u64 d;
    asm("fma.rn.f32x2 %0, %1, %2, %3;" : "=l"(d) : "l"(a), "l"(b), "l"(c));
    return d;
}

// ---------------------------------------------------------------------------
// Select-free value-splitting reduction (validated R14). Lane l's slot s
// holds the partial of row (s ^ v), v=(lane>>2)&7: every round's give is
// slot i+half and the received value is exactly the kept row's partial.
// ---------------------------------------------------------------------------
__device__ __forceinline__ float reduce8_perm(float acc[8])
{
#pragma unroll
    for (int i = 0; i < 4; i++)
        acc[i] += __shfl_xor_sync(0xffffffffu, acc[i + 4], 16);
#pragma unroll
    for (int i = 0; i < 2; i++)
        acc[i] += __shfl_xor_sync(0xffffffffu, acc[i + 2], 8);
    acc[0] += __shfl_xor_sync(0xffffffffu, acc[1], 4);
    acc[0] += __shfl_xor_sync(0xffffffffu, acc[0], 2);
    acc[0] += __shfl_xor_sync(0xffffffffu, acc[0], 1);
    return acc[0];
}

// Packed dot: slot pair (2p,2p+1) accumulated in one f32x2 lane-pair chain.
__device__ __forceinline__ void dot8_packed(const u64 aregp[16], float4 xv,
                                            float acc[8])
{
    u64 xx = pack2(xv.x, xv.x);
    u64 xy = pack2(xv.y, xv.y);
    u64 xz = pack2(xv.z, xv.z);
    u64 xw = pack2(xv.w, xv.w);
#pragma unroll
    for (int p = 0; p < 4; p++) {
        u64 t = mul2(aregp[p * 4 + 0], xx);
        t = fma2(aregp[p * 4 + 1], xy, t);
        t = fma2(aregp[p * 4 + 2], xz, t);
        t = fma2(aregp[p * 4 + 3], xw, t);
        unpack2(acc[2 * p], acc[2 * p + 1], t);
    }
}

// ---------------------------------------------------------------------------
// Kernel 1: per-node scores. Two warps per node (role 0 = src, role 1 = dst).
// THREE nodes per iteration: all three x-row loads issue before any compute
// (MLP=3), then dot+reduce run sequentially reusing ONE acc array so register
// pressure stays inside the 64-reg / 4-block-per-SM residency cap.
// ---------------------------------------------------------------------------
__global__ void __launch_bounds__(256, 4) scores_kernel(
    const float* __restrict__ x,
    const float* __restrict__ aa,
    int n_nodes)
{
    const int lane  = threadIdx.x & 31;
    const int gwarp = (blockIdx.x * blockDim.x + threadIdx.x) >> 5;
    const int nwarp = (gridDim.x * blockDim.x) >> 5;
    const int role  = gwarp & 1;            // 0: src rows, 1: dst rows
    const int wnode0 = gwarp >> 1;
    const int nstep  = nwarp >> 1;

    const int v   = (lane >> 2) & 7;        // value this lane ends holding
    const int sub = lane & 3;               // sub-lane within value group

    // aregp[p*4+f] = packed (row (2p)^v feat f, row (2p+1)^v feat f).
    u64 aregp[16];
    const float4* aa4 = reinterpret_cast<const float4*>(aa);
    {
        const int off = role ? 32 : 0;
#pragma unroll
        for (int p = 0; p < 4; p++) {
            float4 r0 = __ldg(&aa4[((2 * p)     ^ v) * 64 + off + lane]);
            float4 r1 = __ldg(&aa4[((2 * p + 1) ^ v) * 64 + off + lane]);
            aregp[p * 4 + 0] = pack2(r0.x, r1.x);
            aregp[p * 4 + 1] = pack2(r0.y, r1.y);
            aregp[p * 4 + 2] = pack2(r0.z, r1.z);
            aregp[p * 4 + 3] = pack2(r0.w, r1.w);
        }
    }

    const float4* x4 = reinterpret_cast<const float4*>(x);

    int node = wnode0;
    // Main loop: 3 in-range nodes, loads issued before any compute.
    for (; node + 2 * nstep < n_nodes; node += 3 * nstep) {
        const int nodeB = node + nstep;
        const int nodeC = node + 2 * nstep;

        float4 xvA = __ldg(&x4[(size_t)node  * 32 + lane]);
        float4 xvB = __ldg(&x4[(size_t)nodeB * 32 + lane]);
        float4 xvC = __ldg(&x4[(size_t)nodeC * 32 + lane]);

        float acc[8];
        dot8_packed(aregp, xvA, acc);
        float rA = reduce8_perm(acc);
        dot8_packed(aregp, xvB, acc);
        float rB = reduce8_perm(acc);
        dot8_packed(aregp, xvC, acc);
        float rC = reduce8_perm(acc);

        if (role == 0) {
            if (sub == 0) {
                g_srcsum[(size_t)node  * 16 + v] = rA;
                g_srcsum[(size_t)nodeB * 16 + v] = rB;
                g_srcsum[(size_t)nodeC * 16 + v] = rC;
            } else if (sub == 1) {
                g_srcsum[(size_t)node  * 16 + 8 + v] = 0.0f;
                g_srcsum[(size_t)nodeB * 16 + 8 + v] = 0.0f;
                g_srcsum[(size_t)nodeC * 16 + 8 + v] = 0.0f;
            }
        } else {
            if (sub == 0) {
                g_dst[(size_t)node  * 8 + v] = rA;
                g_dst[(size_t)nodeB * 8 + v] = rB;
                g_dst[(size_t)nodeC * 8 + v] = rC;
            }
        }
    }
    // Tail: up to 2 lone nodes.
    for (; node < n_nodes; node += nstep) {
        float4 xvA = __ldg(&x4[(size_t)node * 32 + lane]);
        float acc[8];
        dot8_packed(aregp, xvA, acc);
        float rA = reduce8_perm(acc);
        if (role == 0) {
            if (sub == 0)      g_srcsum[(size_t)node * 16 + v]     = rA;
            else if (sub == 1) g_srcsum[(size_t)node * 16 + 8 + v] = 0.0f;
        } else if (sub == 0) {
            g_dst[(size_t)node * 8 + v] = rA;
        }
    }
}

// ---------------------------------------------------------------------------
// Kernel 2: segment-sum of exp(e). Two threads per edge, one red.v4 each
// (validated L1tex-queue sweet spot — do not batch more edges per thread).
// ---------------------------------------------------------------------------
__global__ void __launch_bounds__(256) sum_kernel(
    const int* __restrict__ row,
    const int* __restrict__ col,
    int n_edges)
{
    int t = blockIdx.x * blockDim.x + threadIdx.x;
    int e = t >> 1;
    int h = t & 1;
    if (e >= n_edges) return;
    int r = __ldg(row + e);
    int c = __ldg(col + e);

    const float4* s4 = reinterpret_cast<const float4*>(g_srcsum);
    const float4* d4 = reinterpret_cast<const float4*>(g_dst);
    float4 a = __ldg(&s4[(size_t)r * 4 + h]);
    float4 b = __ldg(&d4[(size_t)c * 2 + h]);

    float e0 = a.x + b.x, e1 = a.y + b.y, e2 = a.z + b.z, e3 = a.w + b.w;
    e0 = fmaxf(e0, ALPHA_F * e0); e1 = fmaxf(e1, ALPHA_F * e1);
    e2 = fmaxf(e2, ALPHA_F * e2); e3 = fmaxf(e3, ALPHA_F * e3);

    float x0 = __expf(e0), x1 = __expf(e1), x2 = __expf(e2), x3 = __expf(e3);

    float* dst = g_srcsum + (size_t)r * 16 + 8 + 4 * h;
    asm volatile("red.global.add.v4.f32 [%0], {%1,%2,%3,%4};"
                 :: "l"(dst), "f"(x0), "f"(x1), "f"(x2), "f"(x3)
                 : "memory");
}

// ---------------------------------------------------------------------------
// Kernel 3: a[head][e] = exp(e) * rcp(ssum[r][head] + EPS). Reciprocal fused.
// ---------------------------------------------------------------------------
__device__ __forceinline__ float frcp_fast(float v)
{
    float r;
    asm("rcp.approx.ftz.f32 %0, %1;" : "=f"(r) : "f"(v));
    return r;
}

__global__ void __launch_bounds__(256) out_kernel(
    const int* __restrict__ row,
    const int* __restrict__ col,
    float* __restrict__ out,
    int n_edges)
{
    int t = blockIdx.x * blockDim.x + threadIdx.x;
    int e = t >> 1;
    int h = t & 1;
    if (e >= n_edges) return;
    int r = __ldg(row + e);
    int c = __ldg(col + e);

    const float4* s4 = reinterpret_cast<const float4*>(g_srcsum);
    const float4* d4 = reinterpret_cast<const float4*>(g_dst);
    float4 a = __ldg(&s4[(size_t)r * 4 + h]);          // src scores
    float4 s = __ldg(&s4[(size_t)r * 4 + 2 + h]);      // raw ssum (same line)
    float4 b = __ldg(&d4[(size_t)c * 2 + h]);          // dst scores

    float e0 = a.x + b.x, e1 = a.y + b.y, e2 = a.z + b.z, e3 = a.w + b.w;
    e0 = fmaxf(e0, ALPHA_F * e0); e1 = fmaxf(e1, ALPHA_F * e1);
    e2 = fmaxf(e2, ALPHA_F * e2); e3 = fmaxf(e3, ALPHA_F * e3);

    float i0 = frcp_fast(s.x + EPS_F);
    float i1 = frcp_fast(s.y + EPS_F);
    float i2 = frcp_fast(s.z + EPS_F);
    float i3 = frcp_fast(s.w + EPS_F);

    size_t E = (size_t)n_edges;
    float* o = out + (size_t)(4 * h) * E + e;
    o[0 * E] = __expf(e0) * i0;
    o[1 * E] = __expf(e1) * i1;
    o[2 * E] = __expf(e2) * i2;
    o[3 * E] = __expf(e3) * i3;
}

extern "C" void kernel_launch(void* const* d_in, const int* in_sizes, int n_in,
                              void* d_out, int out_size)
{
    const float* x   = (const float*)d_in[0];
    const int*   row = (const int*)  d_in[1];
    const int*   col = (const int*)  d_in[2];
    const float* aa  = (const float*)d_in[3];
    float* out = (float*)d_out;

    int n_nodes = in_sizes[0] / FDIM;   // 100000
    int n_edges = in_sizes[1];          // 1600000

    // 592 = 4 blocks/SM x 148 SMs (residency pinned by launch_bounds).
    scores_kernel<<<592, 256>>>(x, aa, n_nodes);

    int nthreads = 2 * n_edges;
    sum_kernel<<<(nthreads + 255) / 256, 256>>>(row, col, n_edges);
    out_kernel<<<(nthreads + 255) / 256, 256>>>(row, col, out, n_edges);
}